// round 8
// baseline (speedup 1.0000x reference)
#include <cuda_runtime.h>
#include <math.h>

// ---------------- problem constants ----------------
#define B_   2
#define N_   2048
#define D_   1024
#define H_   16
#define DH_  64
#define CC_  64
#define NC_  32
#define CGIT_ 30
#define M_   (B_*N_)
#define LD   68   // smem row stride (floats), multiple of 4 for float4

// ---------------- scratch (device globals; no allocs allowed) ----------------
__device__ __align__(256) float g_Q   [M_*D_];
__device__ __align__(256) float g_K   [M_*D_];
__device__ __align__(256) float g_V   [M_*D_];
__device__ __align__(256) float g_gate[M_*D_];
__device__ __align__(256) float g_O   [M_*D_];
__device__ __align__(256) float g_OG  [M_*D_];
__device__ __align__(256) float g_G1  [M_*DH_];
__device__ __align__(256) float g_logf[M_*H_];
__device__ __align__(256) float g_beta[M_*H_];
__device__ __align__(256) float g_cum [B_*H_*NC_*CC_];
__device__ __align__(256) float g_Hkk [B_*H_*NC_*DH_*DH_];
__device__ __align__(256) float g_Hkv [B_*H_*NC_*DH_*DH_];

// ---------------- generic tiled fp32 GEMM: C[M,N] = A[M,K] @ B[K,N] ----------
// tiles 64x64, k-step 16, 256 threads, 4x4 microtile. mode 1 = sigmoid epilogue.
__global__ __launch_bounds__(256) void gemm64(const float* __restrict__ A,
                                              const float* __restrict__ Bm,
                                              float* __restrict__ C,
                                              int M, int Nc, int K, int mode) {
    __shared__ float As[16][LD];
    __shared__ float Bs[16][LD];
    int bm = blockIdx.y * 64, bn = blockIdx.x * 64;
    int tid = threadIdx.x;
    int tr = tid >> 4, tc = tid & 15;
    int ar = tid >> 2, ac = (tid & 3) << 2;
    int br = tid >> 4, bc = (tid & 15) << 2;
    float acc[4][4];
#pragma unroll
    for (int i = 0; i < 4; i++)
#pragma unroll
        for (int j = 0; j < 4; j++) acc[i][j] = 0.f;

    for (int k0 = 0; k0 < K; k0 += 16) {
        float4 a4 = *(const float4*)(A + (size_t)(bm + ar) * K + k0 + ac);
        As[ac + 0][ar] = a4.x; As[ac + 1][ar] = a4.y;
        As[ac + 2][ar] = a4.z; As[ac + 3][ar] = a4.w;
        *(float4*)&Bs[br][bc] =
            *(const float4*)(Bm + (size_t)(k0 + br) * Nc + bn + bc);
        __syncthreads();
#pragma unroll
        for (int k = 0; k < 16; k++) {
            float4 av = *(const float4*)&As[k][tr * 4];
            float4 bv = *(const float4*)&Bs[k][tc * 4];
            float aa[4] = {av.x, av.y, av.z, av.w};
            float bb[4] = {bv.x, bv.y, bv.z, bv.w};
#pragma unroll
            for (int i = 0; i < 4; i++)
#pragma unroll
                for (int j = 0; j < 4; j++) acc[i][j] += aa[i] * bb[j];
        }
        __syncthreads();
    }
#pragma unroll
    for (int i = 0; i < 4; i++) {
        float4 o4;
        float v0 = acc[i][0], v1 = acc[i][1], v2 = acc[i][2], v3 = acc[i][3];
        if (mode == 1) {
            v0 = 1.f / (1.f + expf(-v0)); v1 = 1.f / (1.f + expf(-v1));
            v2 = 1.f / (1.f + expf(-v2)); v3 = 1.f / (1.f + expf(-v3));
        }
        o4.x = v0; o4.y = v1; o4.z = v2; o4.w = v3;
        *(float4*)(C + (size_t)(bm + tr * 4 + i) * Nc + bn + tc * 4) = o4;
    }
}

// ---------------- f / beta projections: logf = log_sigmoid(x@Wf+delta), beta = sigmoid(x@Wbet)
__global__ __launch_bounds__(256) void fbproj(const float* __restrict__ x,
                                              const float* __restrict__ Wf,
                                              const float* __restrict__ Wbet,
                                              const float* __restrict__ delta,
                                              float* __restrict__ logf,
                                              float* __restrict__ beta) {
    __shared__ __align__(16) float sx[D_];
    int m = blockIdx.x, tid = threadIdx.x;
    *(float4*)&sx[tid * 4] = *(const float4*)&x[(size_t)m * D_ + tid * 4];
    __syncthreads();
    int oid = tid >> 3, part = tid & 7;
    int h = oid & 15;
    const float* W = (oid & 16) ? Wbet : Wf;
    float sum = 0.f;
    for (int d = part; d < D_; d += 8) sum += sx[d] * W[d * H_ + h];
    sum += __shfl_xor_sync(0xffffffffu, sum, 1);
    sum += __shfl_xor_sync(0xffffffffu, sum, 2);
    sum += __shfl_xor_sync(0xffffffffu, sum, 4);
    if (part == 0) {
        if (oid & 16) {
            beta[(size_t)m * H_ + h] = 1.f / (1.f + expf(-sum));
        } else {
            float z = sum + delta[h];
            float ls = (z >= 0.f) ? -log1pf(expf(-z)) : (z - log1pf(expf(z)));
            logf[(size_t)m * H_ + h] = ls;
        }
    }
}

// ---------------- l2 normalize q,k per (row, head), eps=1e-6 ----------------
__global__ __launch_bounds__(256) void normqk(float* __restrict__ Q,
                                              float* __restrict__ K) {
    int gw = (blockIdx.x * 256 + threadIdx.x) >> 5;  // 0..65535
    int lane = threadIdx.x & 31;
    int m = gw >> 4, h = gw & 15;
    size_t base = (size_t)m * D_ + h * 64;
    float a = Q[base + lane], b = Q[base + 32 + lane];
    float ss = a * a + b * b;
#pragma unroll
    for (int o = 16; o; o >>= 1) ss += __shfl_xor_sync(0xffffffffu, ss, o);
    float sc = rsqrtf(ss + 1e-6f);
    Q[base + lane] = a * sc; Q[base + 32 + lane] = b * sc;
    a = K[base + lane]; b = K[base + 32 + lane];
    ss = a * a + b * b;
#pragma unroll
    for (int o = 16; o; o >>= 1) ss += __shfl_xor_sync(0xffffffffu, ss, o);
    sc = rsqrtf(ss + 1e-6f);
    K[base + lane] = a * sc; K[base + 32 + lane] = b * sc;
}

// ---------------- per-chunk inclusive prefix of log_f -----------------------
__global__ void cumf(const float* __restrict__ logf, float* __restrict__ cum) {
    __shared__ float s[64];
    int bhc = blockIdx.x;                 // b*512 + h*32 + c
    int t = threadIdx.x;
    int c = bhc & 31, h = (bhc >> 5) & 15, b = bhc >> 9;
    int m = b * N_ + c * 64 + t;
    s[t] = logf[(size_t)m * H_ + h];
    __syncthreads();
    for (int off = 1; off < 64; off <<= 1) {
        float add = (t >= off) ? s[t - off] : 0.f;
        __syncthreads();
        s[t] += add;
        __syncthreads();
    }
    cum[(size_t)bhc * 64 + t] = s[t];
}

// ---------------- sequential chunk-boundary state pass ----------------------
// grid = 32 (b,h). Stores state BEFORE each chunk into g_Hkk/g_Hkv.
__global__ __launch_bounds__(256) void state_pass(const float* __restrict__ K,
                                                  const float* __restrict__ V,
                                                  const float* __restrict__ beta,
                                                  const float* __restrict__ cum,
                                                  float* __restrict__ Hkk,
                                                  float* __restrict__ Hkv) {
    extern __shared__ float sm[];
    float* sHkk = sm;
    float* sHkv = sm + 64 * LD;
    float* sK   = sm + 2 * 64 * LD;
    float* sV   = sm + 3 * 64 * LD;
    __shared__ __align__(16) float scoef[64];
    __shared__ float s_ecl;
    int bh = blockIdx.x;
    int b = bh >> 4, h = bh & 15;
    int tid = threadIdx.x;
    int ty = tid >> 4, tx = tid & 15;

#pragma unroll
    for (int i = 0; i < 16; i++) {
        int idx = i * 256 + tid; int t = idx >> 6, j = idx & 63;
        sHkk[t * LD + j] = 0.f; sHkv[t * LD + j] = 0.f;
    }
    __syncthreads();

    for (int c = 0; c < NC_; c++) {
        size_t sbase = ((size_t)bh * NC_ + c) * 4096;
        size_t rowbase = ((size_t)(b * N_ + c * 64)) * D_ + h * 64;
#pragma unroll
        for (int i = 0; i < 16; i++) {
            int idx = i * 256 + tid; int t = idx >> 6, j = idx & 63;
            Hkk[sbase + idx] = sHkk[t * LD + j];
            Hkv[sbase + idx] = sHkv[t * LD + j];
            sK[t * LD + j] = K[rowbase + (size_t)t * D_ + j];
            sV[t * LD + j] = V[rowbase + (size_t)t * D_ + j];
        }
        if (tid < 64) {
            size_t cb = ((size_t)bh * NC_ + c) * 64;
            float c63 = cum[cb + 63];
            float cs  = cum[cb + tid];
            float bs  = beta[((size_t)(b * N_ + c * 64 + tid)) * H_ + h];
            scoef[tid] = bs * expf(c63 - cs);
            if (tid == 0) s_ecl = expf(c63);
        }
        __syncthreads();

        float akk[4][4], akv[4][4];
#pragma unroll
        for (int i = 0; i < 4; i++)
#pragma unroll
            for (int j = 0; j < 4; j++) { akk[i][j] = 0.f; akv[i][j] = 0.f; }
        for (int s = 0; s < 64; s++) {
            float cf = scoef[s];
            float a0 = cf * sK[s * LD + 4 * ty + 0];
            float a1 = cf * sK[s * LD + 4 * ty + 1];
            float a2 = cf * sK[s * LD + 4 * ty + 2];
            float a3 = cf * sK[s * LD + 4 * ty + 3];
            float4 bk = *(float4*)&sK[s * LD + 4 * tx];
            float4 bv = *(float4*)&sV[s * LD + 4 * tx];
            float aa[4] = {a0, a1, a2, a3};
            float kk[4] = {bk.x, bk.y, bk.z, bk.w};
            float vv[4] = {bv.x, bv.y, bv.z, bv.w};
#pragma unroll
            for (int i = 0; i < 4; i++)
#pragma unroll
                for (int j = 0; j < 4; j++) {
                    akk[i][j] += aa[i] * kk[j];
                    akv[i][j] += aa[i] * vv[j];
                }
        }
        float ecl = s_ecl;
#pragma unroll
        for (int i = 0; i < 4; i++)
#pragma unroll
            for (int j = 0; j < 4; j++) {
                int r = (4 * ty + i) * LD + 4 * tx + j;
                sHkk[r] = ecl * sHkk[r] + akk[i][j];
                sHkv[r] = ecl * sHkv[r] + akv[i][j];
            }
        __syncthreads();
    }
}

// ---------------- per-chunk batched CG + output -----------------------------
// grid = B*H*NC = 1024. 256 threads. Dynamic smem: 7 matrices of 64xLD floats.
__global__ __launch_bounds__(256) void cg_chunk(const float* __restrict__ Qm,
                                                const float* __restrict__ Km,
                                                const float* __restrict__ Vm,
                                                const float* __restrict__ betap,
                                                const float* __restrict__ cump,
                                                const float* __restrict__ Hkkp,
                                                const float* __restrict__ Hkvp,
                                                const float* __restrict__ lambp,
                                                float* __restrict__ Om) {
    extern __shared__ float sm[];
    float* sK  = sm;
    float* sKt = sm + 64 * LD;
    float* sH  = sm + 2 * 64 * LD;
    float* sP  = sm + 3 * 64 * LD;
    float* sW  = sm + 4 * 64 * LD;
    float* sG  = sm + 5 * 64 * LD;
    float* sAP = sm + 6 * 64 * LD;
    __shared__ __align__(16) float scum[64];
    __shared__ __align__(16) float secum[64];
    __shared__ __align__(16) float slamb[64];
    __shared__ __align__(16) float sbeta[64];

    int bhc = blockIdx.x;
    int c = bhc & 31, h = (bhc >> 5) & 15, b = bhc >> 9;
    int tid = threadIdx.x;
    int ty = tid >> 4, tx = tid & 15;
    size_t rowbase = ((size_t)(b * N_ + c * 64)) * D_ + h * 64;
    size_t hbase = (size_t)bhc * 4096;

#pragma unroll
    for (int i = 0; i < 16; i++) {
        int idx = i * 256 + tid; int t = idx >> 6, j = idx & 63;
        float kv = Km[rowbase + (size_t)t * D_ + j];
        sK[t * LD + j] = kv;
        sKt[j * LD + t] = kv;
        sP[t * LD + j] = Qm[rowbase + (size_t)t * D_ + j];
        sH[t * LD + j] = Hkkp[hbase + idx];
    }
    if (tid < 64) {
        float cv = cump[(size_t)bhc * 64 + tid];
        scum[tid] = cv;
        secum[tid] = expf(cv);
        float lp = lambp[h * 64 + tid];
        slamb[tid] = ((lp > 20.f) ? lp : log1pf(expf(lp))) + 0.25f;
        sbeta[tid] = betap[((size_t)(b * N_ + c * 64 + tid)) * H_ + h];
    }
    __syncthreads();
#pragma unroll
    for (int i = 0; i < 16; i++) {
        int idx = i * 256 + tid; int t = idx >> 6, s = idx & 63;
        sW[t * LD + s] = (s <= t) ? sbeta[s] * expf(scum[t] - scum[s]) : 0.f;
    }

    // per-row CG state in registers: 4 threads per row, 16 cols each
    int warp = tid >> 5, lane = tid & 31;
    int r = warp * 8 + (lane >> 2);
    int quad = lane & 3;
    int col0 = quad * 16;
    float X[16], R[16];
    float rs = 0.f;
#pragma unroll
    for (int u = 0; u < 16; u++) {
        float qv = sP[r * LD + col0 + u];
        R[u] = qv; X[u] = 0.f; rs += qv * qv;
    }
    rs += __shfl_xor_sync(0xffffffffu, rs, 1);
    rs += __shfl_xor_sync(0xffffffffu, rs, 2);

    for (int it = 0; it < CGIT_; it++) {
        __syncthreads();
        // GEMM1: G = (P @ K^T) * W
        {
            float g[4][4];
#pragma unroll
            for (int i = 0; i < 4; i++)
#pragma unroll
                for (int j = 0; j < 4; j++) g[i][j] = 0.f;
            for (int k = 0; k < 64; k++) {
                float a0 = sP[(4 * ty + 0) * LD + k];
                float a1 = sP[(4 * ty + 1) * LD + k];
                float a2 = sP[(4 * ty + 2) * LD + k];
                float a3 = sP[(4 * ty + 3) * LD + k];
                float4 bt = *(float4*)&sKt[k * LD + 4 * tx];
                float aa[4] = {a0, a1, a2, a3};
                float bb[4] = {bt.x, bt.y, bt.z, bt.w};
#pragma unroll
                for (int i = 0; i < 4; i++)
#pragma unroll
                    for (int j = 0; j < 4; j++) g[i][j] += aa[i] * bb[j];
            }
#pragma unroll
            for (int i = 0; i < 4; i++) {
                float4 wv = *(float4*)&sW[(4 * ty + i) * LD + 4 * tx];
                float4 gv;
                gv.x = g[i][0] * wv.x; gv.y = g[i][1] * wv.y;
                gv.z = g[i][2] * wv.z; gv.w = g[i][3] * wv.w;
                *(float4*)&sG[(4 * ty + i) * LD + 4 * tx] = gv;
            }
        }
        __syncthreads();
        // GEMM2: AP = ecum*(P@H0kk) + G@K + lamb*P
        {
            float au[4][4], az[4][4];
#pragma unroll
            for (int i = 0; i < 4; i++)
#pragma unroll
                for (int j = 0; j < 4; j++) { au[i][j] = 0.f; az[i][j] = 0.f; }
            for (int k = 0; k < 64; k++) {
                float p0 = sP[(4 * ty + 0) * LD + k];
                float p1 = sP[(4 * ty + 1) * LD + k];
                float p2 = sP[(4 * ty + 2) * LD + k];
                float p3 = sP[(4 * ty + 3) * LD + k];
                float g0 = sG[(4 * ty + 0) * LD + k];
                float g1 = sG[(4 * ty + 1) * LD + k];
                float g2 = sG[(4 * ty + 2) * LD + k];
                float g3 = sG[(4 * ty + 3) * LD + k];
                float4 h4 = *(float4*)&sH[k * LD + 4 * tx];
                float4 k4 = *(float4*)&sK[k * LD + 4 * tx];
                float pp[4] = {p0, p1, p2, p3};
                float gg[4] = {g0, g1, g2, g3};
                float hh[4] = {h4.x, h4.y, h4.z, h4.w};
                float kk[4] = {k4.x, k4.y, k4.z, k4.w};
#pragma unroll
                for (int i = 0; i < 4; i++)
#pragma unroll
                    for (int j = 0; j < 4; j++) {
                        au[i][j] += pp[i] * hh[j];
                        az[i][j] += gg[i] * kk[j];
                    }
            }
            float4 lv = *(float4*)&slamb[4 * tx];
            float ll[4] = {lv.x, lv.y, lv.z, lv.w};
#pragma unroll
            for (int i = 0; i < 4; i++) {
                float e = secum[4 * ty + i];
                float4 pv = *(float4*)&sP[(4 * ty + i) * LD + 4 * tx];
                float pp[4] = {pv.x, pv.y, pv.z, pv.w};
                float4 apv;
                apv.x = e * au[i][0] + az[i][0] + ll[0] * pp[0];
                apv.y = e * au[i][1] + az[i][1] + ll[1] * pp[1];
                apv.z = e * au[i][2] + az[i][2] + ll[2] * pp[2];
                apv.w = e * au[i][3] + az[i][3] + ll[3] * pp[3];
                *(float4*)&sAP[(4 * ty + i) * LD + 4 * tx] = apv;
            }
        }
        __syncthreads();
        // row phase
        {
            float p[16], ap[16];
#pragma unroll
            for (int u4 = 0; u4 < 4; u4++) {
                float4 pv = *(float4*)&sP[r * LD + col0 + 4 * u4];
                float4 av = *(float4*)&sAP[r * LD + col0 + 4 * u4];
                p[4 * u4 + 0] = pv.x; p[4 * u4 + 1] = pv.y;
                p[4 * u4 + 2] = pv.z; p[4 * u4 + 3] = pv.w;
                ap[4 * u4 + 0] = av.x; ap[4 * u4 + 1] = av.y;
                ap[4 * u4 + 2] = av.z; ap[4 * u4 + 3] = av.w;
            }
            float pAp = 0.f;
#pragma unroll
            for (int u = 0; u < 16; u++) pAp += p[u] * ap[u];
            pAp += __shfl_xor_sync(0xffffffffu, pAp, 1);
            pAp += __shfl_xor_sync(0xffffffffu, pAp, 2);
            float alpha = rs / (pAp + 1e-12f);
            float rsn = 0.f;
#pragma unroll
            for (int u = 0; u < 16; u++) {
                X[u] += alpha * p[u];
                R[u] -= alpha * ap[u];
                rsn += R[u] * R[u];
            }
            rsn += __shfl_xor_sync(0xffffffffu, rsn, 1);
            rsn += __shfl_xor_sync(0xffffffffu, rsn, 2);
            float bcg = rsn / (rs + 1e-12f);
            rs = rsn;
#pragma unroll
            for (int u4 = 0; u4 < 4; u4++) {
                float4 nv;
                nv.x = R[4 * u4 + 0] + bcg * p[4 * u4 + 0];
                nv.y = R[4 * u4 + 1] + bcg * p[4 * u4 + 1];
                nv.z = R[4 * u4 + 2] + bcg * p[4 * u4 + 2];
                nv.w = R[4 * u4 + 3] + bcg * p[4 * u4 + 3];
                *(float4*)&sP[r * LD + col0 + 4 * u4] = nv;
            }
        }
    }
    // ---- output phase: O = ecum*(X@H0kv) + (W*(X K^T)) @ V ----
    // write X into sP (own cells, no race), then reload H0kv and V
#pragma unroll
    for (int u4 = 0; u4 < 4; u4++) {
        float4 xv;
        xv.x = X[4 * u4 + 0]; xv.y = X[4 * u4 + 1];
        xv.z = X[4 * u4 + 2]; xv.w = X[4 * u4 + 3];
        *(float4*)&sP[r * LD + col0 + 4 * u4] = xv;
    }
    __syncthreads();
#pragma unroll
    for (int i = 0; i < 16; i++) {
        int idx = i * 256 + tid; int t = idx >> 6, j = idx & 63;
        sH[t * LD + j] = Hkvp[hbase + idx];
        sAP[t * LD + j] = Vm[rowbase + (size_t)t * D_ + j];
    }
    __syncthreads();
    // G = (X @ K^T) * W
    {
        float g[4][4];
#pragma unroll
        for (int i = 0; i < 4; i++)
#pragma unroll
            for (int j = 0; j < 4; j++) g[i][j] = 0.f;
        for (int k = 0; k < 64; k++) {
            float a0 = sP[(4 * ty + 0) * LD + k];
            float a1 = sP[(4 * ty + 1) * LD + k];
            float a2 = sP[(4 * ty + 2) * LD + k];
            float a3 = sP[(4 * ty + 3) * LD + k];
            float4 bt = *(float4*)&sKt[k * LD + 4 * tx];
            float aa[4] = {a0, a1, a2, a3};
            float bb[4] = {bt.x, bt.y, bt.z, bt.w};
#pragma unroll
            for (int i = 0; i < 4; i++)
#pragma unroll
                for (int j = 0; j < 4; j++) g[i][j] += aa[i] * bb[j];
        }
#pragma unroll
        for (int i = 0; i < 4; i++) {
            float4 wv = *(float4*)&sW[(4 * ty + i) * LD + 4 * tx];
            float4 gv;
            gv.x = g[i][0] * wv.x; gv.y = g[i][1] * wv.y;
            gv.z = g[i][2] * wv.z; gv.w = g[i][3] * wv.w;
            *(float4*)&sG[(4 * ty + i) * LD + 4 * tx] = gv;
        }
    }
    __syncthreads();
    // O = ecum*(X@Hkv) + G@V, store to global
    {
        float au[4][4], az[4][4];
#pragma unroll
        for (int i = 0; i < 4; i++)
#pragma unroll
            for (int j = 0; j < 4; j++) { au[i][j] = 0.f; az[i][j] = 0.f; }
        for (int k = 0; k < 64; k++) {
            float p0 = sP[(4 * ty + 0) * LD + k];
            float p1 = sP[(4 * ty + 1) * LD + k];
            float p2 = sP[(4 * ty + 2) * LD + k];
            float p3 = sP[(4 * ty + 3) * LD + k];
            float g0 = sG[(4 * ty + 0) * LD + k];
            float g1 = sG[(4 * ty + 1) * LD + k];
            float g2 = sG[(4 * ty + 2) * LD + k];
            float g3 = sG[(4 * ty + 3) * LD + k];
            float4 h4 = *(float4*)&sH[k * LD + 4 * tx];
            float4 v4 = *(float4*)&sAP[k * LD + 4 * tx];
            float pp[4] = {p0, p1, p2, p3};
            float gg[4] = {g0, g1, g2, g3};
            float hh[4] = {h4.x, h4.y, h4.z, h4.w};
            float vv[4] = {v4.x, v4.y, v4.z, v4.w};
#pragma unroll
            for (int i = 0; i < 4; i++)
#pragma unroll
                for (int j = 0; j < 4; j++) {
                    au[i][j] += pp[i] * hh[j];
                    az[i][j] += gg[i] * vv[j];
                }
        }
#pragma unroll
        for (int i = 0; i < 4; i++) {
            float e = secum[4 * ty + i];
            float4 ov;
            ov.x = e * au[i][0] + az[i][0];
            ov.y = e * au[i][1] + az[i][1];
            ov.z = e * au[i][2] + az[i][2];
            ov.w = e * au[i][3] + az[i][3];
            *(float4*)(Om + rowbase + (size_t)(4 * ty + i) * D_ + 4 * tx) = ov;
        }
    }
}

// ---------------- gate + grouped RMSNorm epilogue ---------------------------
__global__ __launch_bounds__(256) void epilogue_k(const float* __restrict__ O,
                                                  const float* __restrict__ gate,
                                                  const float* __restrict__ nw,
                                                  float* __restrict__ OG) {
    int gw = (blockIdx.x * 256 + threadIdx.x) >> 5;
    int lane = threadIdx.x & 31;
    int m = gw >> 4, h = gw & 15;
    size_t base = (size_t)m * D_ + h * 64;
    float o0 = O[base + lane] * gate[base + lane];
    float o1 = O[base + 32 + lane] * gate[base + 32 + lane];
    float ss = o0 * o0 + o1 * o1;
#pragma unroll
    for (int o = 16; o; o >>= 1) ss += __shfl_xor_sync(0xffffffffu, ss, o);
    float sc = rsqrtf(ss * (1.f / 64.f) + 1e-5f);
    OG[base + lane]      = o0 * sc * nw[h * 64 + lane];
    OG[base + 32 + lane] = o1 * sc * nw[h * 64 + 32 + lane];
}

// ---------------- launcher --------------------------------------------------
extern "C" void kernel_launch(void* const* d_in, const int* in_sizes, int n_in,
                              void* d_out, int out_size) {
    (void)in_sizes; (void)n_in; (void)out_size;
    const float* x     = (const float*)d_in[0];
    const float* Wq    = (const float*)d_in[1];
    const float* Wk    = (const float*)d_in[2];
    const float* Wv    = (const float*)d_in[3];
    const float* Wf    = (const float*)d_in[4];
    const float* Wbet  = (const float*)d_in[5];
    const float* Wo    = (const float*)d_in[6];
    const float* delta = (const float*)d_in[7];
    const float* lambp = (const float*)d_in[8];
    const float* nw    = (const float*)d_in[9];
    const float* gw1   = (const float*)d_in[10];
    const float* gw2   = (const float*)d_in[11];
    float* out = (float*)d_out;

    void *pQ, *pK, *pV, *pGate, *pO, *pOG, *pG1, *pLogf, *pBeta, *pCum, *pHkk, *pHkv;
    cudaGetSymbolAddress(&pQ,    g_Q);
    cudaGetSymbolAddress(&pK,    g_K);
    cudaGetSymbolAddress(&pV,    g_V);
    cudaGetSymbolAddress(&pGate, g_gate);
    cudaGetSymbolAddress(&pO,    g_O);
    cudaGetSymbolAddress(&pOG,   g_OG);
    cudaGetSymbolAddress(&pG1,   g_G1);
    cudaGetSymbolAddress(&pLogf, g_logf);
    cudaGetSymbolAddress(&pBeta, g_beta);
    cudaGetSymbolAddress(&pCum,  g_cum);
    cudaGetSymbolAddress(&pHkk,  g_Hkk);
    cudaGetSymbolAddress(&pHkv,  g_Hkv);

    const int state_smem = 4 * 64 * LD * 4;   // 69632 B
    const int cg_smem    = 7 * 64 * LD * 4;   // 121856 B
    cudaFuncSetAttribute(state_pass, cudaFuncAttributeMaxDynamicSharedMemorySize, state_smem);
    cudaFuncSetAttribute(cg_chunk,   cudaFuncAttributeMaxDynamicSharedMemorySize, cg_smem);

    dim3 blk(256);
    // projections
    gemm64<<<dim3(16, 64), blk>>>(x, Wq, (float*)pQ, M_, D_, D_, 0);
    gemm64<<<dim3(16, 64), blk>>>(x, Wk, (float*)pK, M_, D_, D_, 0);
    gemm64<<<dim3(16, 64), blk>>>(x, Wv, (float*)pV, M_, D_, D_, 0);
    gemm64<<<dim3(1, 64),  blk>>>(x, gw1, (float*)pG1, M_, 64, D_, 0);
    gemm64<<<dim3(16, 64), blk>>>((const float*)pG1, gw2, (float*)pGate, M_, D_, 64, 1);
    fbproj<<<M_, 256>>>(x, Wf, Wbet, delta, (float*)pLogf, (float*)pBeta);
    normqk<<<8192, 256>>>((float*)pQ, (float*)pK);
    cumf<<<1024, 64>>>((const float*)pLogf, (float*)pCum);
    // sequential boundary states
    state_pass<<<32, 256, state_smem>>>((const float*)pK, (const float*)pV,
                                        (const float*)pBeta, (const float*)pCum,
                                        (float*)pHkk, (float*)pHkv);
    // batched per-chunk CG + output
    cg_chunk<<<1024, 256, cg_smem>>>((const float*)pQ, (const float*)pK,
                                     (const float*)pV, (const float*)pBeta,
                                     (const float*)pCum, (const float*)pHkk,
                                     (const float*)pHkv, lambp, (float*)pO);
    // gate * o, grouped rmsnorm, weight
    epilogue_k<<<8192, 256>>>((const float*)pO, (const float*)pGate, nw, (float*)pOG);
    // final projection
    gemm64<<<dim3(16, 64), blk>>>((const float*)pOG, Wo, out, M_, D_, D_, 0);
}

// round 10
// speedup vs baseline: 1.7126x; 1.7126x over previous
#include <cuda_runtime.h>
#include <math.h>

// ---------------- problem constants ----------------
#define B_    2
#define N_    2048
#define D_    1024
#define H_    16
#define CGIT_ 30
#define M_    (B_*N_)
#define LD    68    // smem row stride for 64-wide tiles
#define GLD   132   // smem row stride for 128-wide tiles

// ---------------- scratch (device globals; no allocs allowed) ----------------
__device__ __align__(256) float g_Q   [M_*D_];
__device__ __align__(256) float g_K   [M_*D_];
__device__ __align__(256) float g_V   [M_*D_];
__device__ __align__(256) float g_gate[M_*D_];
__device__ __align__(256) float g_O   [M_*D_];
__device__ __align__(256) float g_OG  [M_*D_];
__device__ __align__(256) float g_G1  [M_*64];
__device__ __align__(256) float g_logf[M_*H_];
__device__ __align__(256) float g_beta[M_*H_];
__device__ __align__(256) float g_cum [1024*64];
__device__ __align__(256) float g_Hkk [1024*4096];
__device__ __align__(256) float g_Hkv [1024*4096];
__device__ __align__(256) float g_ecl [1024];

// ---------------- f32x2 helpers ----------------
__device__ __forceinline__ void ffma2(unsigned long long& d,
                                      unsigned long long a,
                                      unsigned long long b) {
    asm("fma.rn.f32x2 %0, %1, %2, %3;" : "=l"(d) : "l"(a), "l"(b), "l"(d));
}
__device__ __forceinline__ unsigned long long dup2(float s) {
    unsigned long long d;
    unsigned u = __float_as_uint(s);
    asm("mov.b64 %0, {%1, %1};" : "=l"(d) : "r"(u));
    return d;
}
__device__ __forceinline__ float2 unpk(unsigned long long d) {
    unsigned lo, hi;
    asm("mov.b64 {%0, %1}, %2;" : "=r"(lo), "=r"(hi) : "l"(d));
    return make_float2(__uint_as_float(lo), __uint_as_float(hi));
}

// ---------------- big GEMM: C[M,N]=A[M,K]@B[K,N], 128x128 tiles, f32x2 -----
// mode 1 = sigmoid epilogue. M,N multiples of 128; K multiple of 16.
__global__ __launch_bounds__(256) void gemm128(const float* __restrict__ A,
                                               const float* __restrict__ Bm,
                                               float* __restrict__ C,
                                               int M, int Nc, int K, int mode) {
    __shared__ __align__(16) float As[16][GLD];   // col-major: As[k][row]
    __shared__ __align__(16) float Bs[16][GLD];   // row-major: Bs[k][col]
    int bm = blockIdx.y * 128, bn = blockIdx.x * 128;
    int tid = threadIdx.x;
    int ty = tid >> 4, tx = tid & 15;
    int ar = tid >> 2, ac = (tid & 3) << 2;
    int br = tid >> 4, bc = (tid & 15) << 3;
    unsigned long long acc[8][4];
#pragma unroll
    for (int i = 0; i < 8; i++)
#pragma unroll
        for (int j = 0; j < 4; j++) acc[i][j] = 0ULL;

    for (int k0 = 0; k0 < K; k0 += 16) {
#pragma unroll
        for (int half = 0; half < 2; half++) {
            int r = half * 64 + ar;
            float4 a4 = *(const float4*)(A + (size_t)(bm + r) * K + k0 + ac);
            As[ac + 0][r] = a4.x; As[ac + 1][r] = a4.y;
            As[ac + 2][r] = a4.z; As[ac + 3][r] = a4.w;
        }
        *(float4*)&Bs[br][bc] =
            *(const float4*)(Bm + (size_t)(k0 + br) * Nc + bn + bc);
        *(float4*)&Bs[br][bc + 4] =
            *(const float4*)(Bm + (size_t)(k0 + br) * Nc + bn + bc + 4);
        __syncthreads();
#pragma unroll
        for (int k = 0; k < 16; k++) {
            float4 a0 = *(const float4*)&As[k][ty * 8];
            float4 a1 = *(const float4*)&As[k][ty * 8 + 4];
            ulonglong2 bp0 = *(const ulonglong2*)&Bs[k][tx * 8];
            ulonglong2 bp1 = *(const ulonglong2*)&Bs[k][tx * 8 + 4];
            unsigned long long ad[8];
            ad[0] = dup2(a0.x); ad[1] = dup2(a0.y);
            ad[2] = dup2(a0.z); ad[3] = dup2(a0.w);
            ad[4] = dup2(a1.x); ad[5] = dup2(a1.y);
            ad[6] = dup2(a1.z); ad[7] = dup2(a1.w);
#pragma unroll
            for (int i = 0; i < 8; i++) {
                ffma2(acc[i][0], ad[i], bp0.x);
                ffma2(acc[i][1], ad[i], bp0.y);
                ffma2(acc[i][2], ad[i], bp1.x);
                ffma2(acc[i][3], ad[i], bp1.y);
            }
        }
        __syncthreads();
    }
#pragma unroll
    for (int i = 0; i < 8; i++) {
        float out[8];
#pragma unroll
        for (int j = 0; j < 4; j++) {
            float2 v = unpk(acc[i][j]);
            out[2 * j] = v.x; out[2 * j + 1] = v.y;
        }
        if (mode == 1) {
#pragma unroll
            for (int j = 0; j < 8; j++) out[j] = 1.f / (1.f + expf(-out[j]));
        }
        float4* dst = (float4*)(C + (size_t)(bm + ty * 8 + i) * Nc + bn + tx * 8);
        dst[0] = make_float4(out[0], out[1], out[2], out[3]);
        dst[1] = make_float4(out[4], out[5], out[6], out[7]);
    }
}

// ---------------- G1 = x @ gate_w1  (4096x64, K=1024) -----------------------
__global__ __launch_bounds__(256) void g1proj(const float* __restrict__ x,
                                              const float* __restrict__ W,
                                              float* __restrict__ G1) {
    __shared__ __align__(16) float sx[8][D_];
    int bid = blockIdx.x;   // 512 blocks, 8 rows each
    int tid = threadIdx.x;
    int w = tid >> 5, l = tid & 31;
#pragma unroll
    for (int i = 0; i < 8; i++) {
        int idx = i * 256 + tid;
        int r = idx >> 8, c4 = idx & 255;
        *(float4*)&sx[r][c4 * 4] =
            *(const float4*)(x + (size_t)(bid * 8 + r) * D_ + c4 * 4);
    }
    __syncthreads();
    const float2* W2 = (const float2*)W;  // [D_][32]
    float2 acc = make_float2(0.f, 0.f);
    for (int k = 0; k < D_; k += 4) {
        float x0 = sx[w][k], x1 = sx[w][k + 1], x2 = sx[w][k + 2], x3 = sx[w][k + 3];
        float2 w0 = W2[(size_t)k * 32 + l];
        float2 w1 = W2[(size_t)(k + 1) * 32 + l];
        float2 w2 = W2[(size_t)(k + 2) * 32 + l];
        float2 w3 = W2[(size_t)(k + 3) * 32 + l];
        acc.x += x0 * w0.x; acc.y += x0 * w0.y;
        acc.x += x1 * w1.x; acc.y += x1 * w1.y;
        acc.x += x2 * w2.x; acc.y += x2 * w2.y;
        acc.x += x3 * w3.x; acc.y += x3 * w3.y;
    }
    *(float2*)(G1 + (size_t)(bid * 8 + w) * 64 + 2 * l) = acc;
}

// ---------------- f / beta projections --------------------------------------
__global__ __launch_bounds__(256) void fbproj(const float* __restrict__ x,
                                              const float* __restrict__ Wf,
                                              const float* __restrict__ Wbet,
                                              const float* __restrict__ delta,
                                              float* __restrict__ logf,
                                              float* __restrict__ beta) {
    __shared__ __align__(16) float sx[D_];
    int m = blockIdx.x, tid = threadIdx.x;
    *(float4*)&sx[tid * 4] = *(const float4*)&x[(size_t)m * D_ + tid * 4];
    __syncthreads();
    int oid = tid >> 3, part = tid & 7;
    int h = oid & 15;
    const float* W = (oid & 16) ? Wbet : Wf;
    float sum = 0.f;
    for (int d = part; d < D_; d += 8) sum += sx[d] * W[d * H_ + h];
    sum += __shfl_xor_sync(0xffffffffu, sum, 1);
    sum += __shfl_xor_sync(0xffffffffu, sum, 2);
    sum += __shfl_xor_sync(0xffffffffu, sum, 4);
    if (part == 0) {
        if (oid & 16) {
            beta[(size_t)m * H_ + h] = 1.f / (1.f + expf(-sum));
        } else {
            float z = sum + delta[h];
            float ls = (z >= 0.f) ? -log1pf(expf(-z)) : (z - log1pf(expf(z)));
            logf[(size_t)m * H_ + h] = ls;
        }
    }
}

// ---------------- l2 normalize q,k per (row, head) --------------------------
__global__ __launch_bounds__(256) void normqk(float* __restrict__ Q,
                                              float* __restrict__ K) {
    int gw = (blockIdx.x * 256 + threadIdx.x) >> 5;
    int lane = threadIdx.x & 31;
    int m = gw >> 4, h = gw & 15;
    size_t base = (size_t)m * D_ + h * 64;
    float a = Q[base + lane], b = Q[base + 32 + lane];
    float ss = a * a + b * b;
#pragma unroll
    for (int o = 16; o; o >>= 1) ss += __shfl_xor_sync(0xffffffffu, ss, o);
    float sc = rsqrtf(ss + 1e-6f);
    Q[base + lane] = a * sc; Q[base + 32 + lane] = b * sc;
    a = K[base + lane]; b = K[base + 32 + lane];
    ss = a * a + b * b;
#pragma unroll
    for (int o = 16; o; o >>= 1) ss += __shfl_xor_sync(0xffffffffu, ss, o);
    sc = rsqrtf(ss + 1e-6f);
    K[base + lane] = a * sc; K[base + 32 + lane] = b * sc;
}

// ---------------- per-chunk inclusive prefix of log_f -----------------------
__global__ void cumf(const float* __restrict__ logf, float* __restrict__ cum) {
    __shared__ float s[64];
    int bhc = blockIdx.x;
    int t = threadIdx.x;
    int c = bhc & 31, h = (bhc >> 5) & 15, b = bhc >> 9;
    int m = b * N_ + c * 64 + t;
    s[t] = logf[(size_t)m * H_ + h];
    __syncthreads();
    for (int off = 1; off < 64; off <<= 1) {
        float add = (t >= off) ? s[t - off] : 0.f;
        __syncthreads();
        s[t] += add;
        __syncthreads();
    }
    cum[(size_t)bhc * 64 + t] = s[t];
}

// ---------------- per-chunk outer-product sums (parallel, 1024 CTAs) --------
__global__ __launch_bounds__(256) void chunk_outer(const float* __restrict__ K,
                                                   const float* __restrict__ V,
                                                   const float* __restrict__ beta,
                                                   const float* __restrict__ cum,
                                                   float* __restrict__ Skk,
                                                   float* __restrict__ Skv,
                                                   float* __restrict__ ecl) {
    extern __shared__ float sm[];
    float* sK = sm;
    float* sV = sm + 64 * LD;
    __shared__ __align__(16) float scoef[64];
    int bhc = blockIdx.x;
    int c = bhc & 31, h = (bhc >> 5) & 15, b = bhc >> 9;
    int tid = threadIdx.x;
    int ty = tid >> 4, tx = tid & 15;
    size_t rowbase = ((size_t)(b * N_ + c * 64)) * D_ + h * 64;
#pragma unroll
    for (int i = 0; i < 16; i++) {
        int idx = i * 256 + tid; int t = idx >> 6, j = idx & 63;
        sK[t * LD + j] = K[rowbase + (size_t)t * D_ + j];
        sV[t * LD + j] = V[rowbase + (size_t)t * D_ + j];
    }
    if (tid < 64) {
        size_t cb = (size_t)bhc * 64;
        float c63 = cum[cb + 63];
        float cs  = cum[cb + tid];
        scoef[tid] = beta[((size_t)(b * N_ + c * 64 + tid)) * H_ + h] * expf(c63 - cs);
        if (tid == 0) ecl[bhc] = expf(c63);
    }
    __syncthreads();
    float akk[4][4], akv[4][4];
#pragma unroll
    for (int i = 0; i < 4; i++)
#pragma unroll
        for (int j = 0; j < 4; j++) { akk[i][j] = 0.f; akv[i][j] = 0.f; }
    for (int s = 0; s < 64; s++) {
        float cf = scoef[s];
        float a0 = cf * sK[s * LD + 4 * ty + 0];
        float a1 = cf * sK[s * LD + 4 * ty + 1];
        float a2 = cf * sK[s * LD + 4 * ty + 2];
        float a3 = cf * sK[s * LD + 4 * ty + 3];
        float4 bk = *(float4*)&sK[s * LD + 4 * tx];
        float4 bv = *(float4*)&sV[s * LD + 4 * tx];
        float aa[4] = {a0, a1, a2, a3};
        float kk[4] = {bk.x, bk.y, bk.z, bk.w};
        float vv[4] = {bv.x, bv.y, bv.z, bv.w};
#pragma unroll
        for (int i = 0; i < 4; i++)
#pragma unroll
            for (int j = 0; j < 4; j++) {
                akk[i][j] += aa[i] * kk[j];
                akv[i][j] += aa[i] * vv[j];
            }
    }
    size_t sbase = (size_t)bhc * 4096;
#pragma unroll
    for (int i = 0; i < 4; i++)
#pragma unroll
        for (int j = 0; j < 4; j++) {
            Skk[sbase + (4 * ty + i) * 64 + 4 * tx + j] = akk[i][j];
            Skv[sbase + (4 * ty + i) * 64 + 4 * tx + j] = akv[i][j];
        }
}

// ---------------- in-place scan: S[c] -> H_before[c] (32 CTAs) --------------
__global__ __launch_bounds__(256) void chunk_scan(float* __restrict__ Hkk,
                                                  float* __restrict__ Hkv,
                                                  const float* __restrict__ ecl) {
    int bh = blockIdx.x;
    int tid = threadIdx.x;
    float akk[16], akv[16];
#pragma unroll
    for (int u = 0; u < 16; u++) { akk[u] = 0.f; akv[u] = 0.f; }
    for (int c = 0; c < 32; c++) {
        size_t base = ((size_t)bh * 32 + c) * 4096;
        float skk[16], skv[16];
#pragma unroll
        for (int u = 0; u < 16; u++) {
            int idx = u * 256 + tid;
            skk[u] = Hkk[base + idx]; skv[u] = Hkv[base + idx];
        }
#pragma unroll
        for (int u = 0; u < 16; u++) {
            int idx = u * 256 + tid;
            Hkk[base + idx] = akk[u]; Hkv[base + idx] = akv[u];
        }
        float e = ecl[bh * 32 + c];
#pragma unroll
        for (int u = 0; u < 16; u++) {
            akk[u] = e * akk[u] + skk[u];
            akv[u] = e * akv[u] + skv[u];
        }
    }
}

// ---------------- per-chunk batched CG + output -----------------------------
// grid = 1024, 256 threads, 6 smem matrices (104448 B) -> 2 CTAs/SM.
__global__ __launch_bounds__(256, 2) void cg_chunk(const float* __restrict__ Qm,
                                                   const float* __restrict__ Km,
                                                   const float* __restrict__ Vm,
                                                   const float* __restrict__ betap,
                                                   const float* __restrict__ cump,
                                                   const float* __restrict__ Hkkp,
                                                   const float* __restrict__ Hkvp,
                                                   const float* __restrict__ lambp,
                                                   float* __restrict__ Om) {
    extern __shared__ float sm[];
    float* sK  = sm;
    float* sKt = sm + 64 * LD;
    float* sH  = sm + 2 * 64 * LD;
    float* sP  = sm + 3 * 64 * LD;
    float* sW  = sm + 4 * 64 * LD;
    float* sG  = sm + 5 * 64 * LD;
    __shared__ __align__(16) float scum[64];
    __shared__ __align__(16) float secum[64];
    __shared__ __align__(16) float slamb[64];
    __shared__ __align__(16) float sbeta[64];
    __shared__ int sflag[2];

    int bhc = blockIdx.x;
    int c = bhc & 31, h = (bhc >> 5) & 15, b = bhc >> 9;
    int tid = threadIdx.x;
    int ty = tid >> 4, tx = tid & 15;
    size_t rowbase = ((size_t)(b * N_ + c * 64)) * D_ + h * 64;
    size_t hbase = (size_t)bhc * 4096;

#pragma unroll
    for (int i = 0; i < 16; i++) {
        int idx = i * 256 + tid; int t = idx >> 6, j = idx & 63;
        float kv = Km[rowbase + (size_t)t * D_ + j];
        sK[t * LD + j] = kv;
        sKt[j * LD + t] = kv;
        sP[t * LD + j] = Qm[rowbase + (size_t)t * D_ + j];
        sH[t * LD + j] = Hkkp[hbase + idx];
    }
    if (tid < 64) {
        float cv = cump[(size_t)bhc * 64 + tid];
        scum[tid] = cv;
        secum[tid] = expf(cv);
        float lp = lambp[h * 64 + tid];
        slamb[tid] = ((lp > 20.f) ? lp : log1pf(expf(lp))) + 0.25f;
        sbeta[tid] = betap[((size_t)(b * N_ + c * 64 + tid)) * H_ + h];
    }
    if (tid == 0) { sflag[0] = 0; sflag[1] = 0; }
    __syncthreads();
#pragma unroll
    for (int i = 0; i < 16; i++) {
        int idx = i * 256 + tid; int t = idx >> 6, s = idx & 63;
        sW[t * LD + s] = (s <= t) ? sbeta[s] * expf(scum[t] - scum[s]) : 0.f;
    }

    // per-row CG state: 4 threads per row, 16 cols each
    int lane = tid & 31;
    int r = (tid >> 5) * 8 + (lane >> 2);
    int col0 = (lane & 3) * 16;
    float X[16], R[16];
    float rs = 0.f;
#pragma unroll
    for (int u = 0; u < 16; u++) {
        float qv = sP[r * LD + col0 + u];
        R[u] = qv; X[u] = 0.f; rs += qv * qv;
    }
    rs += __shfl_xor_sync(0xffffffffu, rs, 1);
    rs += __shfl_xor_sync(0xffffffffu, rs, 2);
    float rs0 = rs;

    for (int it = 0; it < CGIT_; it++) {
        __syncthreads();
        if (it > 0 && sflag[(it - 1) & 1] == 0) break;
        if (tid == 0) sflag[it & 1] = 0;
        // GEMM1: G = (P @ K^T) * W
        {
            float g[4][4];
#pragma unroll
            for (int i = 0; i < 4; i++)
#pragma unroll
                for (int j = 0; j < 4; j++) g[i][j] = 0.f;
            for (int k = 0; k < 64; k++) {
                float a0 = sP[(4 * ty + 0) * LD + k];
                float a1 = sP[(4 * ty + 1) * LD + k];
                float a2 = sP[(4 * ty + 2) * LD + k];
                float a3 = sP[(4 * ty + 3) * LD + k];
                float4 bt = *(float4*)&sKt[k * LD + 4 * tx];
                float aa[4] = {a0, a1, a2, a3};
                float bb[4] = {bt.x, bt.y, bt.z, bt.w};
#pragma unroll
                for (int i = 0; i < 4; i++)
#pragma unroll
                    for (int j = 0; j < 4; j++) g[i][j] += aa[i] * bb[j];
            }
#pragma unroll
            for (int i = 0; i < 4; i++) {
                float4 wv = *(float4*)&sW[(4 * ty + i) * LD + 4 * tx];
                float4 gv;
                gv.x = g[i][0] * wv.x; gv.y = g[i][1] * wv.y;
                gv.z = g[i][2] * wv.z; gv.w = g[i][3] * wv.w;
                *(float4*)&sG[(4 * ty + i) * LD + 4 * tx] = gv;
            }
        }
        __syncthreads();
        // GEMM2: AP = ecum*(P@H0kk) + G@K + lamb*P  (into registers)
        float ap[4][4];
        {
            float au[4][4], az[4][4];
#pragma unroll
            for (int i = 0; i < 4; i++)
#pragma unroll
                for (int j = 0; j < 4; j++) { au[i][j] = 0.f; az[i][j] = 0.f; }
            for (int k = 0; k < 64; k++) {
                float p0 = sP[(4 * ty + 0) * LD + k];
                float p1 = sP[(4 * ty + 1) * LD + k];
                float p2 = sP[(4 * ty + 2) * LD + k];
                float p3 = sP[(4 * ty + 3) * LD + k];
                float g0 = sG[(4 * ty + 0) * LD + k];
                float g1 = sG[(4 * ty + 1) * LD + k];
                float g2 = sG[(4 * ty + 2) * LD + k];
                float g3 = sG[(4 * ty + 3) * LD + k];
                float4 h4 = *(float4*)&sH[k * LD + 4 * tx];
                float4 k4 = *(float4*)&sK[k * LD + 4 * tx];
                float pp[4] = {p0, p1, p2, p3};
                float gg[4] = {g0, g1, g2, g3};
                float hh[4] = {h4.x, h4.y, h4.z, h4.w};
                float kk[4] = {k4.x, k4.y, k4.z, k4.w};
#pragma unroll
                for (int i = 0; i < 4; i++)
#pragma unroll
                    for (int j = 0; j < 4; j++) {
                        au[i][j] += pp[i] * hh[j];
                        az[i][j] += gg[i] * kk[j];
                    }
            }
            float4 lv = *(float4*)&slamb[4 * tx];
            float ll[4] = {lv.x, lv.y, lv.z, lv.w};
#pragma unroll
            for (int i = 0; i < 4; i++) {
                float e = secum[4 * ty + i];
                float4 pv = *(float4*)&sP[(4 * ty + i) * LD + 4 * tx];
                float pp[4] = {pv.x, pv.y, pv.z, pv.w};
#pragma unroll
                for (int j = 0; j < 4; j++)
                    ap[i][j] = e * au[i][j] + az[i][j] + ll[j] * pp[j];
            }
        }
        __syncthreads();   // everyone done reading sG
#pragma unroll
        for (int i = 0; i < 4; i++) {
            float4 apv = make_float4(ap[i][0], ap[i][1], ap[i][2], ap[i][3]);
            *(float4*)&sG[(4 * ty + i) * LD + 4 * tx] = apv;   // sG now holds AP
        }
        __syncthreads();
        // row phase
        {
            float p[16], a[16];
#pragma unroll
            for (int u4 = 0; u4 < 4; u4++) {
                float4 pv = *(float4*)&sP[r * LD + col0 + 4 * u4];
                float4 av = *(float4*)&sG[r * LD + col0 + 4 * u4];
                p[4 * u4 + 0] = pv.x; p[4 * u4 + 1] = pv.y;
                p[4 * u4 + 2] = pv.z; p[4 * u4 + 3] = pv.w;
                a[4 * u4 + 0] = av.x; a[4 * u4 + 1] = av.y;
                a[4 * u4 + 2] = av.z; a[4 * u4 + 3] = av.w;
            }
            float pAp = 0.f;
#pragma unroll
            for (int u = 0; u < 16; u++) pAp += p[u] * a[u];
            pAp += __shfl_xor_sync(0xffffffffu, pAp, 1);
            pAp += __shfl_xor_sync(0xffffffffu, pAp, 2);
            float alpha = rs / (pAp + 1e-12f);
            float rsn = 0.f;
#pragma unroll
            for (int u = 0; u < 16; u++) {
                X[u] += alpha * p[u];
                R[u] -= alpha * a[u];
                rsn += R[u] * R[u];
            }
            rsn += __shfl_xor_sync(0xffffffffu, rsn, 1);
            rsn += __shfl_xor_sync(0xffffffffu, rsn, 2);
            float bcg = rsn / (rs + 1e-12f);
            rs = rsn;
#pragma unroll
            for (int u4 = 0; u4 < 4; u4++) {
                float4 nv;
                nv.x = R[4 * u4 + 0] + bcg * p[4 * u4 + 0];
                nv.y = R[4 * u4 + 1] + bcg * p[4 * u4 + 1];
                nv.z = R[4 * u4 + 2] + bcg * p[4 * u4 + 2];
                nv.w = R[4 * u4 + 3] + bcg * p[4 * u4 + 3];
                *(float4*)&sP[r * LD + col0 + 4 * u4] = nv;
            }
            if ((lane & 3) == 0 && rsn > 1e-12f * rs0)
                atomicOr(&sflag[it & 1], 1);
        }
    }

    // ---- output: O = ecum*(X@H0kv) + (W*(X K^T)) @ V ----
#pragma unroll
    for (int u4 = 0; u4 < 4; u4++) {
        float4 xv;
        xv.x = X[4 * u4 + 0]; xv.y = X[4 * u4 + 1];
        xv.z = X[4 * u4 + 2]; xv.w = X[4 * u4 + 3];
        *(float4*)&sP[r * LD + col0 + 4 * u4] = xv;
    }
#pragma unroll
    for (int i = 0; i < 16; i++) {
        int idx = i * 256 + tid; int t = idx >> 6, j = idx & 63;
        sH[t * LD + j] = Hkvp[hbase + idx];
        sK[t * LD + j] = Vm[rowbase + (size_t)t * D_ + j];   // sK now holds V
    }
    __syncthreads();
    // G = (X @ K^T) * W
    {
        float g[4][4];
#pragma unroll
        for (int i = 0; i < 4; i++)
#pragma unroll
            for (int j = 0; j < 4; j++) g[i][j] = 0.f;
        for (int k = 0; k < 64; k++) {
            float a0 = sP[(4 * ty + 0) * LD + k];
            float a1 = sP[(4 * ty + 1) * LD + k];
            float a2 = sP[(4 * ty + 2) * LD + k];
            float a3 = sP[(4 * ty + 3) * LD + k];
            float4 bt = *(float4*)&sKt[k * LD + 4 * tx];
            float aa[4] = {a0, a1, a2, a3};
            float bb[4] = {bt.x, bt.y, bt.z, bt.w};
#pragma unroll
            for (int i = 0; i < 4; i++)
#pragma unroll
                for (int j = 0; j < 4; j++) g[i][j] += aa[i] * bb[j];
        }
#pragma unroll
        for (int i = 0; i < 4; i++) {
            float4 wv = *(float4*)&sW[(4 * ty + i) * LD + 4 * tx];
            float4 gv;
            gv.x = g[i][0] * wv.x; gv.y = g[i][1] * wv.y;
            gv.z = g[i][2] * wv.z; gv.w = g[i][3] * wv.w;
            *(float4*)&sG[(4 * ty + i) * LD + 4 * tx] = gv;
        }
    }
    __syncthreads();
    // O = ecum*(X@Hkv) + G@V
    {
        float au[4][4], az[4][4];
#pragma unroll
        for (int i = 0; i < 4; i++)
#pragma unroll
            for (int j = 0; j < 4; j++) { au[i][j] = 0.f; az[i][j] = 0.f; }
        for (int k = 0; k < 64; k++) {
            float p0 = sP[(4 * ty + 0) * LD + k];
            float p1 = sP[(4 * ty + 1) * LD + k];
            float p2 = sP[(4 * ty + 2) * LD + k];
            float p3 = sP[(4 * ty + 3) * LD + k];
            float g0 = sG[(4 * ty + 0) * LD + k];
            float g1 = sG[(4 * ty + 1) * LD + k];
            float g2 = sG[(4 * ty + 2) * LD + k];
            float g3 = sG[(4 * ty + 3) * LD + k];
            float4 h4 = *(float4*)&sH[k * LD + 4 * tx];
            float4 v4 = *(float4*)&sK[k * LD + 4 * tx];
            float pp[4] = {p0, p1, p2, p3};
            float gg[4] = {g0, g1, g2, g3};
            float hh[4] = {h4.x, h4.y, h4.z, h4.w};
            float vv[4] = {v4.x, v4.y, v4.z, v4.w};
#pragma unroll
            for (int i = 0; i < 4; i++)
#pragma unroll
                for (int j = 0; j < 4; j++) {
                    au[i][j] += pp[i] * hh[j];
                    az[i][j] += gg[i] * vv[j];
                }
        }
#pragma unroll
        for (int i = 0; i < 4; i++) {
            float e = secum[4 * ty + i];
            float4 ov;
            ov.x = e * au[i][0] + az[i][0];
            ov.y = e * au[i][1] + az[i][1];
            ov.z = e * au[i][2] + az[i][2];
            ov.w = e * au[i][3] + az[i][3];
            *(float4*)(Om + rowbase + (size_t)(4 * ty + i) * D_ + 4 * tx) = ov;
        }
    }
}

// ---------------- gate + grouped RMSNorm epilogue ---------------------------
__global__ __launch_bounds__(256) void epilogue_k(const float* __restrict__ O,
                                                  const float* __restrict__ gate,
                                                  const float* __restrict__ nw,
                                                  float* __restrict__ OG) {
    int gw = (blockIdx.x * 256 + threadIdx.x) >> 5;
    int lane = threadIdx.x & 31;
    int m = gw >> 4, h = gw & 15;
    size_t base = (size_t)m * D_ + h * 64;
    float o0 = O[base + lane] * gate[base + lane];
    float o1 = O[base + 32 + lane] * gate[base + 32 + lane];
    float ss = o0 * o0 + o1 * o1;
#pragma unroll
    for (int o = 16; o; o >>= 1) ss += __shfl_xor_sync(0xffffffffu, ss, o);
    float sc = rsqrtf(ss * (1.f / 64.f) + 1e-5f);
    OG[base + lane]      = o0 * sc * nw[h * 64 + lane];
    OG[base + 32 + lane] = o1 * sc * nw[h * 64 + 32 + lane];
}

// ---------------- launcher --------------------------------------------------
extern "C" void kernel_launch(void* const* d_in, const int* in_sizes, int n_in,
                              void* d_out, int out_size) {
    (void)in_sizes; (void)n_in; (void)out_size;
    const float* x     = (const float*)d_in[0];
    const float* Wq    = (const float*)d_in[1];
    const float* Wk    = (const float*)d_in[2];
    const float* Wv    = (const float*)d_in[3];
    const float* Wf    = (const float*)d_in[4];
    const float* Wbet  = (const float*)d_in[5];
    const float* Wo    = (const float*)d_in[6];
    const float* delta = (const float*)d_in[7];
    const float* lambp = (const float*)d_in[8];
    const float* nw    = (const float*)d_in[9];
    const float* gw1   = (const float*)d_in[10];
    const float* gw2   = (const float*)d_in[11];
    float* out = (float*)d_out;

    void *pQ, *pK, *pV, *pGate, *pO, *pOG, *pG1, *pLogf, *pBeta, *pCum, *pHkk, *pHkv, *pEcl;
    cudaGetSymbolAddress(&pQ,    g_Q);
    cudaGetSymbolAddress(&pK,    g_K);
    cudaGetSymbolAddress(&pV,    g_V);
    cudaGetSymbolAddress(&pGate, g_gate);
    cudaGetSymbolAddress(&pO,    g_O);
    cudaGetSymbolAddress(&pOG,   g_OG);
    cudaGetSymbolAddress(&pG1,   g_G1);
    cudaGetSymbolAddress(&pLogf, g_logf);
    cudaGetSymbolAddress(&pBeta, g_beta);
    cudaGetSymbolAddress(&pCum,  g_cum);
    cudaGetSymbolAddress(&pHkk,  g_Hkk);
    cudaGetSymbolAddress(&pHkv,  g_Hkv);
    cudaGetSymbolAddress(&pEcl,  g_ecl);

    const int outer_smem = 2 * 64 * LD * 4;   // 34816 B
    const int cg_smem    = 6 * 64 * LD * 4;   // 104448 B
    cudaFuncSetAttribute(cg_chunk, cudaFuncAttributeMaxDynamicSharedMemorySize, cg_smem);

    dim3 blk(256);
    dim3 gbig(D_ / 128, M_ / 128);            // (8, 32)
    // projections
    gemm128<<<gbig, blk>>>(x, Wq, (float*)pQ, M_, D_, D_, 0);
    gemm128<<<gbig, blk>>>(x, Wk, (float*)pK, M_, D_, D_, 0);
    gemm128<<<gbig, blk>>>(x, Wv, (float*)pV, M_, D_, D_, 0);
    g1proj<<<M_ / 8, blk>>>(x, gw1, (float*)pG1);
    gemm128<<<gbig, blk>>>((const float*)pG1, gw2, (float*)pGate, M_, D_, 64, 1);
    fbproj<<<M_, 256>>>(x, Wf, Wbet, delta, (float*)pLogf, (float*)pBeta);
    normqk<<<8192, 256>>>((float*)pQ, (float*)pK);
    cumf<<<1024, 64>>>((const float*)pLogf, (float*)pCum);
    // parallel per-chunk outer products, then in-place scan to H_before
    chunk_outer<<<1024, 256, outer_smem>>>((const float*)pK, (const float*)pV,
                                           (const float*)pBeta, (const float*)pCum,
                                           (float*)pHkk, (float*)pHkv, (float*)pEcl);
    chunk_scan<<<32, 256>>>((float*)pHkk, (float*)pHkv, (const float*)pEcl);
    // batched per-chunk CG + output
    cg_chunk<<<1024, 256, cg_smem>>>((const float*)pQ, (const float*)pK,
                                     (const float*)pV, (const float*)pBeta,
                                     (const float*)pCum, (const float*)pHkk,
                                     (const float*)pHkv, lambp, (float*)pO);
    // gate * o, grouped rmsnorm, weight
    epilogue_k<<<8192, 256>>>((const float*)pO, (const float*)pGate, nw, (float*)pOG);
    // final projection
    gemm128<<<gbig, blk>>>((const float*)pOG, Wo, out, M_, D_, D_, 0);
}

// round 11
// speedup vs baseline: 1.8739x; 1.0942x over previous
#include <cuda_runtime.h>
#include <math.h>

// ---------------- problem constants ----------------
#define B_    2
#define N_    2048
#define D_    1024
#define H_    16
#define CGIT_ 30
#define M_    (B_*N_)
#define LD    68    // smem row stride for 64-wide tiles
#define GLD   132   // smem row stride for 128-wide tiles
#define CG_TOL 1e-8f

// ---------------- scratch (device globals; no allocs allowed) ----------------
__device__ __align__(256) float g_Q   [M_*D_];
__device__ __align__(256) float g_K   [M_*D_];
__device__ __align__(256) float g_V   [M_*D_];
__device__ __align__(256) float g_gate[M_*D_];
__device__ __align__(256) float g_OG  [M_*D_];
__device__ __align__(256) float g_G1  [M_*64];
__device__ __align__(256) float g_G1p [8*M_*64];
__device__ __align__(256) float g_logf[M_*H_];
__device__ __align__(256) float g_beta[M_*H_];
__device__ __align__(256) float g_cum [1024*64];
__device__ __align__(256) float g_Hkk [1024*4096];
__device__ __align__(256) float g_Hkv [1024*4096];
__device__ __align__(256) float g_ecl [1024];

// ---------------- f32x2 helpers ----------------
__device__ __forceinline__ void ffma2(unsigned long long& d,
                                      unsigned long long a,
                                      unsigned long long b) {
    asm("fma.rn.f32x2 %0, %1, %2, %3;" : "=l"(d) : "l"(a), "l"(b), "l"(d));
}
__device__ __forceinline__ unsigned long long dup2(float s) {
    unsigned long long d;
    unsigned u = __float_as_uint(s);
    asm("mov.b64 %0, {%1, %1};" : "=l"(d) : "r"(u));
    return d;
}
__device__ __forceinline__ float2 unpk(unsigned long long d) {
    unsigned lo, hi;
    asm("mov.b64 {%0, %1}, %2;" : "=r"(lo), "=r"(hi) : "l"(d));
    return make_float2(__uint_as_float(lo), __uint_as_float(hi));
}

// ---------------- big GEMM: C[M,N]=A[M,K]@B[K,N], 128x128 tiles, f32x2 -----
__global__ __launch_bounds__(256) void gemm128(const float* __restrict__ A,
                                               const float* __restrict__ Bm,
                                               float* __restrict__ C,
                                               int M, int Nc, int K, int mode) {
    __shared__ __align__(16) float As[16][GLD];   // col-major: As[k][row]
    __shared__ __align__(16) float Bs[16][GLD];   // row-major: Bs[k][col]
    int bm = blockIdx.y * 128, bn = blockIdx.x * 128;
    int tid = threadIdx.x;
    int ty = tid >> 4, tx = tid & 15;
    int ar = tid >> 2, ac = (tid & 3) << 2;
    int br = tid >> 4, bc = (tid & 15) << 3;
    unsigned long long acc[8][4];
#pragma unroll
    for (int i = 0; i < 8; i++)
#pragma unroll
        for (int j = 0; j < 4; j++) acc[i][j] = 0ULL;

    for (int k0 = 0; k0 < K; k0 += 16) {
#pragma unroll
        for (int half = 0; half < 2; half++) {
            int r = half * 64 + ar;
            float4 a4 = *(const float4*)(A + (size_t)(bm + r) * K + k0 + ac);
            As[ac + 0][r] = a4.x; As[ac + 1][r] = a4.y;
            As[ac + 2][r] = a4.z; As[ac + 3][r] = a4.w;
        }
        *(float4*)&Bs[br][bc] =
            *(const float4*)(Bm + (size_t)(k0 + br) * Nc + bn + bc);
        *(float4*)&Bs[br][bc + 4] =
            *(const float4*)(Bm + (size_t)(k0 + br) * Nc + bn + bc + 4);
        __syncthreads();
#pragma unroll
        for (int k = 0; k < 16; k++) {
            float4 a0 = *(const float4*)&As[k][ty * 8];
            float4 a1 = *(const float4*)&As[k][ty * 8 + 4];
            ulonglong2 bp0 = *(const ulonglong2*)&Bs[k][tx * 8];
            ulonglong2 bp1 = *(const ulonglong2*)&Bs[k][tx * 8 + 4];
            unsigned long long ad[8];
            ad[0] = dup2(a0.x); ad[1] = dup2(a0.y);
            ad[2] = dup2(a0.z); ad[3] = dup2(a0.w);
            ad[4] = dup2(a1.x); ad[5] = dup2(a1.y);
            ad[6] = dup2(a1.z); ad[7] = dup2(a1.w);
#pragma unroll
            for (int i = 0; i < 8; i++) {
                ffma2(acc[i][0], ad[i], bp0.x);
                ffma2(acc[i][1], ad[i], bp0.y);
                ffma2(acc[i][2], ad[i], bp1.x);
                ffma2(acc[i][3], ad[i], bp1.y);
            }
        }
        __syncthreads();
    }
#pragma unroll
    for (int i = 0; i < 8; i++) {
        float out[8];
#pragma unroll
        for (int j = 0; j < 4; j++) {
            float2 v = unpk(acc[i][j]);
            out[2 * j] = v.x; out[2 * j + 1] = v.y;
        }
        if (mode == 1) {
#pragma unroll
            for (int j = 0; j < 8; j++) out[j] = 1.f / (1.f + expf(-out[j]));
        }
        float4* dst = (float4*)(C + (size_t)(bm + ty * 8 + i) * Nc + bn + tx * 8);
        dst[0] = make_float4(out[0], out[1], out[2], out[3]);
        dst[1] = make_float4(out[4], out[5], out[6], out[7]);
    }
}

// ---------------- G1 split-K partials: part[ks] = x[:,ksl] @ W[ksl,:] -------
__global__ __launch_bounds__(256) void g1part(const float* __restrict__ x,
                                              const float* __restrict__ W,
                                              float* __restrict__ part) {
    __shared__ __align__(16) float As[16][GLD];
    __shared__ __align__(16) float Bs[16][LD];
    int ks = blockIdx.x, rb = blockIdx.y;
    int tid = threadIdx.x;
    int ty = tid >> 4, tx = tid & 15;     // rows 8*ty.., cols 4*tx..
    int ar = tid >> 2, ac = (tid & 3) << 2;
    int br = tid >> 4, bc = (tid & 15) << 2;
    unsigned long long acc[8][2];
#pragma unroll
    for (int i = 0; i < 8; i++) { acc[i][0] = 0ULL; acc[i][1] = 0ULL; }

    for (int k0 = 0; k0 < 128; k0 += 16) {
#pragma unroll
        for (int half = 0; half < 2; half++) {
            int r = half * 64 + ar;
            float4 a4 = *(const float4*)(x + (size_t)(rb * 128 + r) * D_ +
                                         ks * 128 + k0 + ac);
            As[ac + 0][r] = a4.x; As[ac + 1][r] = a4.y;
            As[ac + 2][r] = a4.z; As[ac + 3][r] = a4.w;
        }
        *(float4*)&Bs[br][bc] =
            *(const float4*)(W + (size_t)(ks * 128 + k0 + br) * 64 + bc);
        __syncthreads();
#pragma unroll
        for (int k = 0; k < 16; k++) {
            float4 a0 = *(const float4*)&As[k][ty * 8];
            float4 a1 = *(const float4*)&As[k][ty * 8 + 4];
            ulonglong2 bp = *(const ulonglong2*)&Bs[k][tx * 4];
            unsigned long long ad[8];
            ad[0] = dup2(a0.x); ad[1] = dup2(a0.y);
            ad[2] = dup2(a0.z); ad[3] = dup2(a0.w);
            ad[4] = dup2(a1.x); ad[5] = dup2(a1.y);
            ad[6] = dup2(a1.z); ad[7] = dup2(a1.w);
#pragma unroll
            for (int i = 0; i < 8; i++) {
                ffma2(acc[i][0], ad[i], bp.x);
                ffma2(acc[i][1], ad[i], bp.y);
            }
        }
        __syncthreads();
    }
    float* dst = part + (size_t)ks * (M_ * 64);
#pragma unroll
    for (int i = 0; i < 8; i++) {
        float2 v0 = unpk(acc[i][0]), v1 = unpk(acc[i][1]);
        *(float4*)(dst + (size_t)(rb * 128 + ty * 8 + i) * 64 + tx * 4) =
            make_float4(v0.x, v0.y, v1.x, v1.y);
    }
}

__global__ __launch_bounds__(256) void g1reduce(const float* __restrict__ part,
                                                float* __restrict__ G1) {
    int idx = blockIdx.x * 256 + threadIdx.x;
    float s = 0.f;
#pragma unroll
    for (int ks = 0; ks < 8; ks++) s += part[(size_t)ks * (M_ * 64) + idx];
    G1[idx] = s;
}

// ---------------- f / beta projections --------------------------------------
__global__ __launch_bounds__(256) void fbproj(const float* __restrict__ x,
                                              const float* __restrict__ Wf,
                                              const float* __restrict__ Wbet,
                                              const float* __restrict__ delta,
                                              float* __restrict__ logf,
                                              float* __restrict__ beta) {
    __shared__ __align__(16) float sx[D_];
    int m = blockIdx.x, tid = threadIdx.x;
    *(float4*)&sx[tid * 4] = *(const float4*)&x[(size_t)m * D_ + tid * 4];
    __syncthreads();
    int oid = tid >> 3, part = tid & 7;
    int h = oid & 15;
    const float* W = (oid & 16) ? Wbet : Wf;
    float sum = 0.f;
    for (int d = part; d < D_; d += 8) sum += sx[d] * W[d * H_ + h];
    sum += __shfl_xor_sync(0xffffffffu, sum, 1);
    sum += __shfl_xor_sync(0xffffffffu, sum, 2);
    sum += __shfl_xor_sync(0xffffffffu, sum, 4);
    if (part == 0) {
        if (oid & 16) {
            beta[(size_t)m * H_ + h] = 1.f / (1.f + expf(-sum));
        } else {
            float z = sum + delta[h];
            float ls = (z >= 0.f) ? -log1pf(expf(-z)) : (z - log1pf(expf(z)));
            logf[(size_t)m * H_ + h] = ls;
        }
    }
}

// ---------------- l2 normalize q,k per (row, head) --------------------------
__global__ __launch_bounds__(256) void normqk(float* __restrict__ Q,
                                              float* __restrict__ K) {
    int gw = (blockIdx.x * 256 + threadIdx.x) >> 5;
    int lane = threadIdx.x & 31;
    int m = gw >> 4, h = gw & 15;
    size_t base = (size_t)m * D_ + h * 64;
    float a = Q[base + lane], b = Q[base + 32 + lane];
    float ss = a * a + b * b;
#pragma unroll
    for (int o = 16; o; o >>= 1) ss += __shfl_xor_sync(0xffffffffu, ss, o);
    float sc = rsqrtf(ss + 1e-6f);
    Q[base + lane] = a * sc; Q[base + 32 + lane] = b * sc;
    a = K[base + lane]; b = K[base + 32 + lane];
    ss = a * a + b * b;
#pragma unroll
    for (int o = 16; o; o >>= 1) ss += __shfl_xor_sync(0xffffffffu, ss, o);
    sc = rsqrtf(ss + 1e-6f);
    K[base + lane] = a * sc; K[base + 32 + lane] = b * sc;
}

// ---------------- per-chunk inclusive prefix of log_f -----------------------
__global__ void cumf(const float* __restrict__ logf, float* __restrict__ cum) {
    __shared__ float s[64];
    int bhc = blockIdx.x;
    int t = threadIdx.x;
    int c = bhc & 31, h = (bhc >> 5) & 15, b = bhc >> 9;
    int m = b * N_ + c * 64 + t;
    s[t] = logf[(size_t)m * H_ + h];
    __syncthreads();
    for (int off = 1; off < 64; off <<= 1) {
        float add = (t >= off) ? s[t - off] : 0.f;
        __syncthreads();
        s[t] += add;
        __syncthreads();
    }
    cum[(size_t)bhc * 64 + t] = s[t];
}

// ---------------- per-chunk outer-product sums (parallel, 1024 CTAs) --------
__global__ __launch_bounds__(256) void chunk_outer(const float* __restrict__ K,
                                                   const float* __restrict__ V,
                                                   const float* __restrict__ beta,
                                                   const float* __restrict__ cum,
                                                   float* __restrict__ Skk,
                                                   float* __restrict__ Skv,
                                                   float* __restrict__ ecl) {
    extern __shared__ float sm[];
    float* sK = sm;
    float* sV = sm + 64 * LD;
    __shared__ __align__(16) float scoef[64];
    int bhc = blockIdx.x;
    int c = bhc & 31, h = (bhc >> 5) & 15, b = bhc >> 9;
    int tid = threadIdx.x;
    int ty = tid >> 4, tx = tid & 15;
    size_t rowbase = ((size_t)(b * N_ + c * 64)) * D_ + h * 64;
#pragma unroll
    for (int i = 0; i < 16; i++) {
        int idx = i * 256 + tid; int t = idx >> 6, j = idx & 63;
        sK[t * LD + j] = K[rowbase + (size_t)t * D_ + j];
        sV[t * LD + j] = V[rowbase + (size_t)t * D_ + j];
    }
    if (tid < 64) {
        size_t cb = (size_t)bhc * 64;
        float c63 = cum[cb + 63];
        float cs  = cum[cb + tid];
        scoef[tid] = beta[((size_t)(b * N_ + c * 64 + tid)) * H_ + h] * expf(c63 - cs);
        if (tid == 0) ecl[bhc] = expf(c63);
    }
    __syncthreads();
    float akk[4][4], akv[4][4];
#pragma unroll
    for (int i = 0; i < 4; i++)
#pragma unroll
        for (int j = 0; j < 4; j++) { akk[i][j] = 0.f; akv[i][j] = 0.f; }
    for (int s = 0; s < 64; s++) {
        float cf = scoef[s];
        float a0 = cf * sK[s * LD + 4 * ty + 0];
        float a1 = cf * sK[s * LD + 4 * ty + 1];
        float a2 = cf * sK[s * LD + 4 * ty + 2];
        float a3 = cf * sK[s * LD + 4 * ty + 3];
        float4 bk = *(float4*)&sK[s * LD + 4 * tx];
        float4 bv = *(float4*)&sV[s * LD + 4 * tx];
        float aa[4] = {a0, a1, a2, a3};
        float kk[4] = {bk.x, bk.y, bk.z, bk.w};
        float vv[4] = {bv.x, bv.y, bv.z, bv.w};
#pragma unroll
        for (int i = 0; i < 4; i++)
#pragma unroll
            for (int j = 0; j < 4; j++) {
                akk[i][j] += aa[i] * kk[j];
                akv[i][j] += aa[i] * vv[j];
            }
    }
    size_t sbase = (size_t)bhc * 4096;
#pragma unroll
    for (int i = 0; i < 4; i++)
#pragma unroll
        for (int j = 0; j < 4; j++) {
            Skk[sbase + (4 * ty + i) * 64 + 4 * tx + j] = akk[i][j];
            Skv[sbase + (4 * ty + i) * 64 + 4 * tx + j] = akv[i][j];
        }
}

// ---------------- in-place scan: S[c] -> H_before[c] (32 CTAs) --------------
__global__ __launch_bounds__(256) void chunk_scan(float* __restrict__ Hkk,
                                                  float* __restrict__ Hkv,
                                                  const float* __restrict__ ecl) {
    int bh = blockIdx.x;
    int tid = threadIdx.x;
    float akk[16], akv[16];
#pragma unroll
    for (int u = 0; u < 16; u++) { akk[u] = 0.f; akv[u] = 0.f; }
    for (int c = 0; c < 32; c++) {
        size_t base = ((size_t)bh * 32 + c) * 4096;
        float skk[16], skv[16];
#pragma unroll
        for (int u = 0; u < 16; u++) {
            int idx = u * 256 + tid;
            skk[u] = Hkk[base + idx]; skv[u] = Hkv[base + idx];
        }
#pragma unroll
        for (int u = 0; u < 16; u++) {
            int idx = u * 256 + tid;
            Hkk[base + idx] = akk[u]; Hkv[base + idx] = akv[u];
        }
        float e = ecl[bh * 32 + c];
#pragma unroll
        for (int u = 0; u < 16; u++) {
            akk[u] = e * akk[u] + skk[u];
            akv[u] = e * akv[u] + skv[u];
        }
    }
}

// ---------------- per-chunk batched PCG + output + fused epilogue -----------
// grid = 1024, 256 threads, 6 smem matrices (104448 B) -> 2 CTAs/SM.
__global__ __launch_bounds__(256, 2) void cg_chunk(const float* __restrict__ Qm,
                                                   const float* __restrict__ Km,
                                                   const float* __restrict__ Vm,
                                                   const float* __restrict__ betap,
                                                   const float* __restrict__ cump,
                                                   const float* __restrict__ Hkkp,
                                                   const float* __restrict__ Hkvp,
                                                   const float* __restrict__ lambp,
                                                   const float* __restrict__ gatep,
                                                   const float* __restrict__ nwp,
                                                   float* __restrict__ OGm) {
    extern __shared__ float sm[];
    float* sK  = sm;
    float* sKt = sm + 64 * LD;
    float* sH  = sm + 2 * 64 * LD;
    float* sP  = sm + 3 * 64 * LD;
    float* sW  = sm + 4 * 64 * LD;
    float* sG  = sm + 5 * 64 * LD;
    __shared__ __align__(16) float scum[64];
    __shared__ __align__(16) float secum[64];
    __shared__ __align__(16) float slamb[64];
    __shared__ __align__(16) float sbeta[64];
    __shared__ int sflag[2];

    int bhc = blockIdx.x;
    int c = bhc & 31, h = (bhc >> 5) & 15, b = bhc >> 9;
    int tid = threadIdx.x;
    int ty = tid >> 4, tx = tid & 15;
    size_t rowbase = ((size_t)(b * N_ + c * 64)) * D_ + h * 64;
    size_t hbase = (size_t)bhc * 4096;

#pragma unroll
    for (int i = 0; i < 16; i++) {
        int idx = i * 256 + tid; int t = idx >> 6, j = idx & 63;
        float kv = Km[rowbase + (size_t)t * D_ + j];
        sK[t * LD + j] = kv;
        sKt[j * LD + t] = kv;
        sP[t * LD + j] = Qm[rowbase + (size_t)t * D_ + j];
        sH[t * LD + j] = Hkkp[hbase + idx];
    }
    if (tid < 64) {
        float cv = cump[(size_t)bhc * 64 + tid];
        scum[tid] = cv;
        secum[tid] = expf(cv);
        float lp = lambp[h * 64 + tid];
        slamb[tid] = ((lp > 20.f) ? lp : log1pf(expf(lp))) + 0.25f;
        sbeta[tid] = betap[((size_t)(b * N_ + c * 64 + tid)) * H_ + h];
    }
    if (tid == 0) { sflag[0] = 0; sflag[1] = 0; }
    __syncthreads();
#pragma unroll
    for (int i = 0; i < 16; i++) {
        int idx = i * 256 + tid; int t = idx >> 6, s = idx & 63;
        sW[t * LD + s] = (s <= t) ? sbeta[s] * expf(scum[t] - scum[s]) : 0.f;
    }
    __syncthreads();

    // per-row PCG state: 4 threads per row, 16 cols each
    int lane = tid & 31;
    int r = (tid >> 5) * 8 + (lane >> 2);
    int col0 = (lane & 3) * 16;

    // Jacobi diag: D[r][j] = lamb_j + ecum_r*H0[j][j] + sum_{s<=r} W[r][s]*K[s][j]^2
    float invD[16];
    {
        float dv[16];
        float er = secum[r];
#pragma unroll
        for (int u = 0; u < 16; u++) {
            int j = col0 + u;
            dv[u] = slamb[j] + er * sH[j * LD + j];
        }
        for (int s = 0; s <= r; s++) {
            float w = sW[r * LD + s];
#pragma unroll
            for (int u4 = 0; u4 < 4; u4++) {
                float4 kv = *(float4*)&sK[s * LD + col0 + 4 * u4];
                dv[4 * u4 + 0] += w * kv.x * kv.x;
                dv[4 * u4 + 1] += w * kv.y * kv.y;
                dv[4 * u4 + 2] += w * kv.z * kv.z;
                dv[4 * u4 + 3] += w * kv.w * kv.w;
            }
        }
#pragma unroll
        for (int u = 0; u < 16; u++) invD[u] = 1.f / dv[u];
    }

    float X[16], R[16];
    float rs0 = 0.f, rho = 0.f;
#pragma unroll
    for (int u = 0; u < 16; u++) {
        float qv = sP[r * LD + col0 + u];
        R[u] = qv; X[u] = 0.f;
        rs0 += qv * qv;
        rho += qv * qv * invD[u];
    }
    rs0 += __shfl_xor_sync(0xffffffffu, rs0, 1);
    rs0 += __shfl_xor_sync(0xffffffffu, rs0, 2);
    rho += __shfl_xor_sync(0xffffffffu, rho, 1);
    rho += __shfl_xor_sync(0xffffffffu, rho, 2);
    // p0 = z0 = invD * r0   (each thread owns its cells of sP)
#pragma unroll
    for (int u = 0; u < 16; u++) sP[r * LD + col0 + u] = invD[u] * R[u];

    for (int it = 0; it < CGIT_; it++) {
        __syncthreads();
        if (it > 0 && sflag[(it - 1) & 1] == 0) break;
        if (tid == 0) sflag[it & 1] = 0;
        // GEMM1: G = (P @ K^T) * W
        {
            float g[4][4];
#pragma unroll
            for (int i = 0; i < 4; i++)
#pragma unroll
                for (int j = 0; j < 4; j++) g[i][j] = 0.f;
            for (int k = 0; k < 64; k++) {
                float a0 = sP[(4 * ty + 0) * LD + k];
                float a1 = sP[(4 * ty + 1) * LD + k];
                float a2 = sP[(4 * ty + 2) * LD + k];
                float a3 = sP[(4 * ty + 3) * LD + k];
                float4 bt = *(float4*)&sKt[k * LD + 4 * tx];
                float aa[4] = {a0, a1, a2, a3};
                float bb[4] = {bt.x, bt.y, bt.z, bt.w};
#pragma unroll
                for (int i = 0; i < 4; i++)
#pragma unroll
                    for (int j = 0; j < 4; j++) g[i][j] += aa[i] * bb[j];
            }
#pragma unroll
            for (int i = 0; i < 4; i++) {
                float4 wv = *(float4*)&sW[(4 * ty + i) * LD + 4 * tx];
                float4 gv;
                gv.x = g[i][0] * wv.x; gv.y = g[i][1] * wv.y;
                gv.z = g[i][2] * wv.z; gv.w = g[i][3] * wv.w;
                *(float4*)&sG[(4 * ty + i) * LD + 4 * tx] = gv;
            }
        }
        __syncthreads();
        // GEMM2: AP = ecum*(P@H0kk) + G@K + lamb*P  (into registers)
        float ap[4][4];
        {
            float au[4][4], az[4][4];
#pragma unroll
            for (int i = 0; i < 4; i++)
#pragma unroll
                for (int j = 0; j < 4; j++) { au[i][j] = 0.f; az[i][j] = 0.f; }
            for (int k = 0; k < 64; k++) {
                float p0 = sP[(4 * ty + 0) * LD + k];
                float p1 = sP[(4 * ty + 1) * LD + k];
                float p2 = sP[(4 * ty + 2) * LD + k];
                float p3 = sP[(4 * ty + 3) * LD + k];
                float g0 = sG[(4 * ty + 0) * LD + k];
                float g1 = sG[(4 * ty + 1) * LD + k];
                float g2 = sG[(4 * ty + 2) * LD + k];
                float g3 = sG[(4 * ty + 3) * LD + k];
                float4 h4 = *(float4*)&sH[k * LD + 4 * tx];
                float4 k4 = *(float4*)&sK[k * LD + 4 * tx];
                float pp[4] = {p0, p1, p2, p3};
                float gg[4] = {g0, g1, g2, g3};
                float hh[4] = {h4.x, h4.y, h4.z, h4.w};
                float kk[4] = {k4.x, k4.y, k4.z, k4.w};
#pragma unroll
                for (int i = 0; i < 4; i++)
#pragma unroll
                    for (int j = 0; j < 4; j++) {
                        au[i][j] += pp[i] * hh[j];
                        az[i][j] += gg[i] * kk[j];
                    }
            }
            float4 lv = *(float4*)&slamb[4 * tx];
            float ll[4] = {lv.x, lv.y, lv.z, lv.w};
#pragma unroll
            for (int i = 0; i < 4; i++) {
                float e = secum[4 * ty + i];
                float4 pv = *(float4*)&sP[(4 * ty + i) * LD + 4 * tx];
                float pp[4] = {pv.x, pv.y, pv.z, pv.w};
#pragma unroll
                for (int j = 0; j < 4; j++)
                    ap[i][j] = e * au[i][j] + az[i][j] + ll[j] * pp[j];
            }
        }
        __syncthreads();   // everyone done reading sG
#pragma unroll
        for (int i = 0; i < 4; i++) {
            float4 apv = make_float4(ap[i][0], ap[i][1], ap[i][2], ap[i][3]);
            *(float4*)&sG[(4 * ty + i) * LD + 4 * tx] = apv;   // sG now holds AP
        }
        __syncthreads();
        // row phase (PCG)
        {
            float p[16], a[16];
#pragma unroll
            for (int u4 = 0; u4 < 4; u4++) {
                float4 pv = *(float4*)&sP[r * LD + col0 + 4 * u4];
                float4 av = *(float4*)&sG[r * LD + col0 + 4 * u4];
                p[4 * u4 + 0] = pv.x; p[4 * u4 + 1] = pv.y;
                p[4 * u4 + 2] = pv.z; p[4 * u4 + 3] = pv.w;
                a[4 * u4 + 0] = av.x; a[4 * u4 + 1] = av.y;
                a[4 * u4 + 2] = av.z; a[4 * u4 + 3] = av.w;
            }
            float pAp = 0.f;
#pragma unroll
            for (int u = 0; u < 16; u++) pAp += p[u] * a[u];
            pAp += __shfl_xor_sync(0xffffffffu, pAp, 1);
            pAp += __shfl_xor_sync(0xffffffffu, pAp, 2);
            float alpha = rho / (pAp + 1e-12f);
            float rr = 0.f, rhon = 0.f;
#pragma unroll
            for (int u = 0; u < 16; u++) {
                X[u] += alpha * p[u];
                R[u] -= alpha * a[u];
                rr += R[u] * R[u];
                rhon += R[u] * R[u] * invD[u];
            }
            rr += __shfl_xor_sync(0xffffffffu, rr, 1);
            rr += __shfl_xor_sync(0xffffffffu, rr, 2);
            rhon += __shfl_xor_sync(0xffffffffu, rhon, 1);
            rhon += __shfl_xor_sync(0xffffffffu, rhon, 2);
            float bcg = rhon / (rho + 1e-12f);
            rho = rhon;
#pragma unroll
            for (int u4 = 0; u4 < 4; u4++) {
                float4 nv;
                nv.x = invD[4 * u4 + 0] * R[4 * u4 + 0] + bcg * p[4 * u4 + 0];
                nv.y = invD[4 * u4 + 1] * R[4 * u4 + 1] + bcg * p[4 * u4 + 1];
                nv.z = invD[4 * u4 + 2] * R[4 * u4 + 2] + bcg * p[4 * u4 + 2];
                nv.w = invD[4 * u4 + 3] * R[4 * u4 + 3] + bcg * p[4 * u4 + 3];
                *(float4*)&sP[r * LD + col0 + 4 * u4] = nv;
            }
            if ((lane & 3) == 0 && rr > CG_TOL * rs0)
                atomicOr(&sflag[it & 1], 1);
        }
    }

    // ---- output: O = ecum*(X@H0kv) + (W*(X K^T)) @ V, then gate+RMSNorm ----
#pragma unroll
    for (int u4 = 0; u4 < 4; u4++) {
        float4 xv;
        xv.x = X[4 * u4 + 0]; xv.y = X[4 * u4 + 1];
        xv.z = X[4 * u4 + 2]; xv.w = X[4 * u4 + 3];
        *(float4*)&sP[r * LD + col0 + 4 * u4] = xv;
    }
#pragma unroll
    for (int i = 0; i < 16; i++) {
        int idx = i * 256 + tid; int t = idx >> 6, j = idx & 63;
        sH[t * LD + j] = Hkvp[hbase + idx];
        sK[t * LD + j] = Vm[rowbase + (size_t)t * D_ + j];   // sK now holds V
    }
    __syncthreads();
    // G = (X @ K^T) * W
    {
        float g[4][4];
#pragma unroll
        for (int i = 0; i < 4; i++)
#pragma unroll
            for (int j = 0; j < 4; j++) g[i][j] = 0.f;
        for (int k = 0; k < 64; k++) {
            float a0 = sP[(4 * ty + 0) * LD + k];
            float a1 = sP[(4 * ty + 1) * LD + k];
            float a2 = sP[(4 * ty + 2) * LD + k];
            float a3 = sP[(4 * ty + 3) * LD + k];
            float4 bt = *(float4*)&sKt[k * LD + 4 * tx];
            float aa[4] = {a0, a1, a2, a3};
            float bb[4] = {bt.x, bt.y, bt.z, bt.w};
#pragma unroll
            for (int i = 0; i < 4; i++)
#pragma unroll
                for (int j = 0; j < 4; j++) g[i][j] += aa[i] * bb[j];
        }
#pragma unroll
        for (int i = 0; i < 4; i++) {
            float4 wv = *(float4*)&sW[(4 * ty + i) * LD + 4 * tx];
            float4 gv;
            gv.x = g[i][0] * wv.x; gv.y = g[i][1] * wv.y;
            gv.z = g[i][2] * wv.z; gv.w = g[i][3] * wv.w;
            *(float4*)&sG[(4 * ty + i) * LD + 4 * tx] = gv;
        }
    }
    __syncthreads();
    // O = ecum*(X@Hkv) + G@V, fused gate + grouped RMSNorm + weight, store OG
    {
        float au[4][4], az[4][4];
#pragma unroll
        for (int i = 0; i < 4; i++)
#pragma unroll
            for (int j = 0; j < 4; j++) { au[i][j] = 0.f; az[i][j] = 0.f; }
        for (int k = 0; k < 64; k++) {
            float p0 = sP[(4 * ty + 0) * LD + k];
            float p1 = sP[(4 * ty + 1) * LD + k];
            float p2 = sP[(4 * ty + 2) * LD + k];
            float p3 = sP[(4 * ty + 3) * LD + k];
            float g0 = sG[(4 * ty + 0) * LD + k];
            float g1 = sG[(4 * ty + 1) * LD + k];
            float g2 = sG[(4 * ty + 2) * LD + k];
            float g3 = sG[(4 * ty + 3) * LD + k];
            float4 h4 = *(float4*)&sH[k * LD + 4 * tx];
            float4 v4 = *(float4*)&sK[k * LD + 4 * tx];
            float pp[4] = {p0, p1, p2, p3};
            float gg[4] = {g0, g1, g2, g3};
            float hh[4] = {h4.x, h4.y, h4.z, h4.w};
            float vv[4] = {v4.x, v4.y, v4.z, v4.w};
#pragma unroll
            for (int i = 0; i < 4; i++)
#pragma unroll
                for (int j = 0; j < 4; j++) {
                    au[i][j] += pp[i] * hh[j];
                    az[i][j] += gg[i] * vv[j];
                }
        }
        float4 nw4 = *(const float4*)&nwp[h * 64 + 4 * tx];
        float nn[4] = {nw4.x, nw4.y, nw4.z, nw4.w};
#pragma unroll
        for (int i = 0; i < 4; i++) {
            float e = secum[4 * ty + i];
            float4 g4 = *(const float4*)(gatep + rowbase +
                                         (size_t)(4 * ty + i) * D_ + 4 * tx);
            float og[4];
            og[0] = (e * au[i][0] + az[i][0]) * g4.x;
            og[1] = (e * au[i][1] + az[i][1]) * g4.y;
            og[2] = (e * au[i][2] + az[i][2]) * g4.z;
            og[3] = (e * au[i][3] + az[i][3]) * g4.w;
            float ss = og[0] * og[0] + og[1] * og[1] + og[2] * og[2] + og[3] * og[3];
            // row 4ty+i lives on a half-warp (same ty, tx=0..15) -> xor 1,2,4,8
            ss += __shfl_xor_sync(0xffffffffu, ss, 1);
            ss += __shfl_xor_sync(0xffffffffu, ss, 2);
            ss += __shfl_xor_sync(0xffffffffu, ss, 4);
            ss += __shfl_xor_sync(0xffffffffu, ss, 8);
            float sc = rsqrtf(ss * (1.f / 64.f) + 1e-5f);
            float4 ov;
            ov.x = og[0] * sc * nn[0];
            ov.y = og[1] * sc * nn[1];
            ov.z = og[2] * sc * nn[2];
            ov.w = og[3] * sc * nn[3];
            *(float4*)(OGm + rowbase + (size_t)(4 * ty + i) * D_ + 4 * tx) = ov;
        }
    }
}

// ---------------- launcher --------------------------------------------------
extern "C" void kernel_launch(void* const* d_in, const int* in_sizes, int n_in,
                              void* d_out, int out_size) {
    (void)in_sizes; (void)n_in; (void)out_size;
    const float* x     = (const float*)d_in[0];
    const float* Wq    = (const float*)d_in[1];
    const float* Wk    = (const float*)d_in[2];
    const float* Wv    = (const float*)d_in[3];
    const float* Wf    = (const float*)d_in[4];
    const float* Wbet  = (const float*)d_in[5];
    const float* Wo    = (const float*)d_in[6];
    const float* delta = (const float*)d_in[7];
    const float* lambp = (const float*)d_in[8];
    const float* nw    = (const float*)d_in[9];
    const float* gw1   = (const float*)d_in[10];
    const float* gw2   = (const float*)d_in[11];
    float* out = (float*)d_out;

    void *pQ, *pK, *pV, *pGate, *pOG, *pG1, *pG1p, *pLogf, *pBeta, *pCum,
         *pHkk, *pHkv, *pEcl;
    cudaGetSymbolAddress(&pQ,    g_Q);
    cudaGetSymbolAddress(&pK,    g_K);
    cudaGetSymbolAddress(&pV,    g_V);
    cudaGetSymbolAddress(&pGate, g_gate);
    cudaGetSymbolAddress(&pOG,   g_OG);
    cudaGetSymbolAddress(&pG1,   g_G1);
    cudaGetSymbolAddress(&pG1p,  g_G1p);
    cudaGetSymbolAddress(&pLogf, g_logf);
    cudaGetSymbolAddress(&pBeta, g_beta);
    cudaGetSymbolAddress(&pCum,  g_cum);
    cudaGetSymbolAddress(&pHkk,  g_Hkk);
    cudaGetSymbolAddress(&pHkv,  g_Hkv);
    cudaGetSymbolAddress(&pEcl,  g_ecl);

    const int outer_smem = 2 * 64 * LD * 4;   // 34816 B
    const int cg_smem    = 6 * 64 * LD * 4;   // 104448 B
    cudaFuncSetAttribute(cg_chunk, cudaFuncAttributeMaxDynamicSharedMemorySize, cg_smem);

    dim3 blk(256);
    dim3 gbig(D_ / 128, M_ / 128);            // (8, 32)
    // projections
    gemm128<<<gbig, blk>>>(x, Wq, (float*)pQ, M_, D_, D_, 0);
    gemm128<<<gbig, blk>>>(x, Wk, (float*)pK, M_, D_, D_, 0);
    gemm128<<<gbig, blk>>>(x, Wv, (float*)pV, M_, D_, D_, 0);
    g1part<<<dim3(8, 32), blk>>>(x, gw1, (float*)pG1p);
    g1reduce<<<(M_ * 64) / 256, blk>>>((const float*)pG1p, (float*)pG1);
    gemm128<<<gbig, blk>>>((const float*)pG1, gw2, (float*)pGate, M_, D_, 64, 1);
    fbproj<<<M_, 256>>>(x, Wf, Wbet, delta, (float*)pLogf, (float*)pBeta);
    normqk<<<8192, 256>>>((float*)pQ, (float*)pK);
    cumf<<<1024, 64>>>((const float*)pLogf, (float*)pCum);
    // parallel per-chunk outer products, then in-place scan to H_before
    chunk_outer<<<1024, 256, outer_smem>>>((const float*)pK, (const float*)pV,
                                           (const float*)pBeta, (const float*)pCum,
                                           (float*)pHkk, (float*)pHkv, (float*)pEcl);
    chunk_scan<<<32, 256>>>((float*)pHkk, (float*)pHkv, (const float*)pEcl);
    // batched per-chunk PCG + output + fused epilogue
    cg_chunk<<<1024, 256, cg_smem>>>((const float*)pQ, (const float*)pK,
                                     (const float*)pV, (const float*)pBeta,
                                     (const float*)pCum, (const float*)pHkk,
                                     (const float*)pHkv, lambp,
                                     (const float*)pGate, nw, (float*)pOG);
    // final projection
    gemm128<<<gbig, blk>>>((const float*)pOG, Wo, out, M_, D_, D_, 0);
}